// round 3
// baseline (speedup 1.0000x reference)
#include <cuda_runtime.h>

// Problem constants (fixed shapes from reference setup_inputs)
#define BB 32
#define CC 4
#define HH 512
#define WW 512
#define PLANE (HH * WW)            // 262144
#define R 10
#define WIN (2 * R + 1)            // 21
#define WINSQ (WIN * WIN)          // 441
#define MAXPTS 65536
#define PT_GRID 8704               // >= expected point count (~8389), 1 pt/block typical
#define PT_BLOCK 448               // >= 441, 14 warps

// Gaussian LUT: exp(-0.5*k^2), k = 0..10 (sigma = 1)
__constant__ float c_g[R + 1] = {
    1.0f,
    6.0653065971e-01f,
    1.3533528324e-01f,
    1.1108996538e-02f,
    3.3546262790e-04f,
    3.7266531720e-06f,
    1.5229979745e-08f,
    2.2897348457e-11f,
    1.2664165549e-14f,
    2.5767571100e-18f,
    1.9287498480e-22f
};

// Scratch (static __device__ allocation; zero-initialized at module load).
// INVARIANT maintained across calls/replays: g_scratch all-zero, g_cnt == 0,
// g_mbits all-zero at kernel_launch entry (k_zero_reset restores it at the end).
__device__ float        g_scratch[BB * PLANE];   // unnormalized G, only windows touched
__device__ unsigned int g_pts[MAXPTS];           // packed points: (b<<18) | (h*512+w)
__device__ unsigned int g_cnt;                   // atomic fill counter (reset by k_zero_reset)
__device__ unsigned int g_n;                     // snapshot of min(g_cnt, MAXPTS), set by k_splat_max
__device__ unsigned int g_mbits[BB];             // per-batch max as uint bits (vals >= 0)

// ---------------------------------------------------------------------------
// Vectorized copy of the whole tensor; channel 2 is written as zeros and its
// positive entries are pushed into the global point list.
__global__ void k_copy_collect(const float* __restrict__ x, float* __restrict__ out) {
    int idx = blockIdx.x * blockDim.x + threadIdx.x;      // float4 index
    int f = idx << 2;                                     // element index (< 2^26)
    int plane = f >> 18;                                  // PLANE = 2^18
    int c = plane & 3;

    float4 v = reinterpret_cast<const float4*>(x)[idx];

    if (c == 2) {
        int b = plane >> 2;
        int off = f & (PLANE - 1);
        reinterpret_cast<float4*>(out)[idx] = make_float4(0.f, 0.f, 0.f, 0.f);
        float vals[4] = {v.x, v.y, v.z, v.w};
        #pragma unroll
        for (int k = 0; k < 4; k++) {
            if (vals[k] > 0.f) {
                unsigned int p = ((unsigned)b << 18) | (unsigned)(off + k);
                unsigned int i = atomicAdd(&g_cnt, 1u);
                if (i < MAXPTS) g_pts[i] = p;
            }
        }
    } else {
        reinterpret_cast<float4*>(out)[idx] = v;
    }
}

// ---------------------------------------------------------------------------
__device__ __forceinline__ void decode_pt(unsigned int pt, int& b, int& h, int& w) {
    b = (int)(pt >> 18);
    int o = (int)(pt & 0x3FFFFu);
    h = o >> 9;
    w = o & 511;
}

// Splat separable Gaussian weights into scratch with atomics AND compute the
// per-batch max in the same pass.
//
// Max trick: atomicAdd returns the pre-add value; all weights are positive, so
// a pixel's running value is monotone increasing and the chronologically last
// adder observes (old + wgt) == final pixel value. Every candidate is <= its
// pixel's final value, and each pixel's final value IS some thread's candidate.
// Hence max over all candidates == max over pixels of the final scratch.
// Block-reduce the candidates, then one atomicMax per point.
__global__ void k_splat_max() {
    __shared__ float red[PT_BLOCK / 32];
    unsigned int n = min(g_cnt, (unsigned int)MAXPTS);
    if (blockIdx.x == 0 && threadIdx.x == 0) g_n = n;   // snapshot for later kernels
    int t = threadIdx.x;
    for (unsigned int p = blockIdx.x; p < n; p += gridDim.x) {
        int b, h, w; decode_pt(g_pts[p], b, h, w);
        float cand = 0.f;
        if (t < WINSQ) {
            int dy = t / WIN - R, dx = t - (t / WIN) * WIN - R;
            int y = h + dy, xx = w + dx;
            if ((unsigned)y < HH && (unsigned)xx < WW) {
                float wgt = c_g[dy < 0 ? -dy : dy] * c_g[dx < 0 ? -dx : dx];
                float old = atomicAdd(&g_scratch[b * PLANE + y * WW + xx], wgt);
                cand = old + wgt;
            }
        }
        #pragma unroll
        for (int s = 16; s; s >>= 1) cand = fmaxf(cand, __shfl_xor_sync(0xFFFFFFFFu, cand, s));
        if ((t & 31) == 0) red[t >> 5] = cand;
        __syncthreads();
        if (t < 32) {
            float m = (t < PT_BLOCK / 32) ? red[t] : 0.f;
            #pragma unroll
            for (int s = 16; s; s >>= 1) m = fmaxf(m, __shfl_xor_sync(0xFFFFFFFFu, m, s));
            if (t == 0) atomicMax(&g_mbits[b], __float_as_uint(m));
        }
        __syncthreads();
    }
}

// Write normalized windows into out channel 2. Overlapping windows write the
// same value (scratch finalized, m fixed) -> benign idempotent races.
__global__ void k_write(float* __restrict__ out) {
    unsigned int n = g_n;
    int t = threadIdx.x;
    for (unsigned int p = blockIdx.x; p < n; p += gridDim.x) {
        int b, h, w; decode_pt(g_pts[p], b, h, w);
        float m = __uint_as_float(g_mbits[b]);
        float inv = (m > 0.f) ? (1.0f / m) : 1.0f;
        if (t < WINSQ) {
            int dy = t / WIN - R, dx = t - (t / WIN) * WIN - R;
            int y = h + dy, xx = w + dx;
            if ((unsigned)y < HH && (unsigned)xx < WW) {
                out[(b * CC + 2) * PLANE + y * WW + xx] =
                    g_scratch[b * PLANE + y * WW + xx] * inv;
            }
        }
    }
}

// Restore the all-zero invariant for the next replay: zero exactly the
// splatted windows (same set splat touched), reset the counter and maxes.
__global__ void k_zero_reset() {
    unsigned int n = g_n;
    int t = threadIdx.x;
    if (blockIdx.x == 0) {
        if (t == 0) g_cnt = 0u;
        if (t < BB) g_mbits[t] = 0u;
    }
    for (unsigned int p = blockIdx.x; p < n; p += gridDim.x) {
        int b, h, w; decode_pt(g_pts[p], b, h, w);
        if (t < WINSQ) {
            int dy = t / WIN - R, dx = t - (t / WIN) * WIN - R;
            int y = h + dy, xx = w + dx;
            if ((unsigned)y < HH && (unsigned)xx < WW)
                g_scratch[b * PLANE + y * WW + xx] = 0.f;
        }
    }
}

// ---------------------------------------------------------------------------
extern "C" void kernel_launch(void* const* d_in, const int* in_sizes, int n_in,
                              void* d_out, int out_size) {
    const float* x = (const float*)d_in[0];
    float* out = (float*)d_out;

    int n_f4 = (BB * CC * PLANE) / 4;          // 8,388,608
    k_copy_collect<<<n_f4 / 256, 256>>>(x, out);

    k_splat_max<<<PT_GRID, PT_BLOCK>>>();
    k_write<<<PT_GRID, PT_BLOCK>>>(out);
    k_zero_reset<<<PT_GRID, PT_BLOCK>>>();
}

// round 4
// speedup vs baseline: 1.0665x; 1.0665x over previous
#include <cuda_runtime.h>

// Problem constants (fixed shapes from reference setup_inputs)
#define BB 32
#define CC 4
#define HH 512
#define WW 512
#define PLANE (HH * WW)            // 262144
#define R 10
#define WIN (2 * R + 1)            // 21
#define WINSQ (WIN * WIN)          // 441
#define MAXPTS 65536
#define PT_BLOCK 256               // 8 warps/block, warp-per-point
#define PT_GRID 1100               // 8800 warps >= expected ~8400 points (one wave)
#define NITER 14                   // ceil(441/32)

// Gaussian LUT: exp(-0.5*k^2), k = 0..10 (sigma = 1). Device global (L1-cached).
__device__ const float d_g[R + 1] = {
    1.0f,
    6.0653065971e-01f,
    1.3533528324e-01f,
    1.1108996538e-02f,
    3.3546262790e-04f,
    3.7266531720e-06f,
    1.5229979745e-08f,
    2.2897348457e-11f,
    1.2664165549e-14f,
    2.5767571100e-18f,
    1.9287498480e-22f
};

// Scratch (static __device__ allocation; zero-initialized at module load).
// INVARIANT across calls/replays: g_scratch all-zero, g_cnt == 0, g_mbits
// all-zero at kernel_launch entry (k_zero_reset restores it at the end).
__device__ float        g_scratch[BB * PLANE];
__device__ unsigned int g_pts[MAXPTS];           // packed: (b<<18) | (h*512+w)
__device__ unsigned int g_cnt;
__device__ unsigned int g_n;                     // snapshot, set by k_splat_max
__device__ unsigned int g_mbits[BB];             // per-batch max (uint bits, vals >= 0)

// ---------------------------------------------------------------------------
// Vectorized copy; channel 2 written as zeros, positives pushed to point list.
__global__ void k_copy_collect(const float* __restrict__ x, float* __restrict__ out) {
    int idx = blockIdx.x * blockDim.x + threadIdx.x;      // float4 index
    int f = idx << 2;
    int plane = f >> 18;                                  // PLANE = 2^18
    int c = plane & 3;

    float4 v = reinterpret_cast<const float4*>(x)[idx];

    if (c == 2) {
        int b = plane >> 2;
        int off = f & (PLANE - 1);
        reinterpret_cast<float4*>(out)[idx] = make_float4(0.f, 0.f, 0.f, 0.f);
        float vals[4] = {v.x, v.y, v.z, v.w};
        #pragma unroll
        for (int k = 0; k < 4; k++) {
            if (vals[k] > 0.f) {
                unsigned int p = ((unsigned)b << 18) | (unsigned)(off + k);
                unsigned int i = atomicAdd(&g_cnt, 1u);
                if (i < MAXPTS) g_pts[i] = p;
            }
        }
    } else {
        reinterpret_cast<float4*>(out)[idx] = v;
    }
}

// ---------------------------------------------------------------------------
__device__ __forceinline__ void decode_pt(unsigned int pt, int& b, int& h, int& w) {
    b = (int)(pt >> 18);
    int o = (int)(pt & 0x3FFFFu);
    h = o >> 9;
    w = o & 511;
}

// Build the 441-entry separable weight table in shared memory (once per block).
__device__ __forceinline__ void build_wtab(float* wtab) {
    for (int k = threadIdx.x; k < WINSQ; k += PT_BLOCK) {
        int dy = k / WIN - R;
        int dx = k - (k / WIN) * WIN - R;
        wtab[k] = d_g[dy < 0 ? -dy : dy] * d_g[dx < 0 ? -dx : dx];
    }
    __syncthreads();
}

// Splat + per-batch max in one pass. Warp-per-point.
// Max trick: atomicAdd returns pre-add value; weights positive => running
// value monotone => max over all (old+wgt) candidates == max of final scratch.
__global__ void k_splat_max() {
    __shared__ float wtab[WINSQ];
    build_wtab(wtab);

    unsigned int n = min(g_cnt, (unsigned int)MAXPTS);
    if (blockIdx.x == 0 && threadIdx.x == 0) g_n = n;

    int lane = threadIdx.x & 31;
    unsigned int gwarp = blockIdx.x * (PT_BLOCK / 32) + (threadIdx.x >> 5);
    unsigned int nwarps = gridDim.x * (PT_BLOCK / 32);

    for (unsigned int p = gwarp; p < n; p += nwarps) {
        int b, h, w; decode_pt(g_pts[p], b, h, w);
        float cand = 0.f;
        #pragma unroll
        for (int it = 0; it < NITER; it++) {
            int k = it * 32 + lane;
            if (k < WINSQ) {
                int dy = k / WIN - R;
                int dx = k - (k / WIN) * WIN - R;
                int y = h + dy, xx = w + dx;
                if ((unsigned)y < HH && (unsigned)xx < WW) {
                    float wgt = wtab[k];
                    float old = atomicAdd(&g_scratch[b * PLANE + y * WW + xx], wgt);
                    cand = fmaxf(cand, old + wgt);
                }
            }
        }
        #pragma unroll
        for (int s = 16; s; s >>= 1)
            cand = fmaxf(cand, __shfl_xor_sync(0xFFFFFFFFu, cand, s));
        if (lane == 0) atomicMax(&g_mbits[b], __float_as_uint(cand));
    }
}

// Write normalized windows into out channel 2. Overlapping windows write the
// same value (scratch finalized, m fixed) -> benign idempotent races.
__global__ void k_write(float* __restrict__ out) {
    unsigned int n = g_n;
    int lane = threadIdx.x & 31;
    unsigned int gwarp = blockIdx.x * (PT_BLOCK / 32) + (threadIdx.x >> 5);
    unsigned int nwarps = gridDim.x * (PT_BLOCK / 32);

    for (unsigned int p = gwarp; p < n; p += nwarps) {
        int b, h, w; decode_pt(g_pts[p], b, h, w);
        float m = __uint_as_float(g_mbits[b]);
        float inv = (m > 0.f) ? (1.0f / m) : 1.0f;
        #pragma unroll
        for (int it = 0; it < NITER; it++) {
            int k = it * 32 + lane;
            if (k < WINSQ) {
                int dy = k / WIN - R;
                int dx = k - (k / WIN) * WIN - R;
                int y = h + dy, xx = w + dx;
                if ((unsigned)y < HH && (unsigned)xx < WW) {
                    out[(b * CC + 2) * PLANE + y * WW + xx] =
                        g_scratch[b * PLANE + y * WW + xx] * inv;
                }
            }
        }
    }
}

// Restore all-zero invariant for next replay (zero exactly the splatted windows).
__global__ void k_zero_reset() {
    unsigned int n = g_n;
    if (blockIdx.x == 0) {
        if (threadIdx.x == 0) g_cnt = 0u;
        if (threadIdx.x < BB) g_mbits[threadIdx.x] = 0u;
    }
    int lane = threadIdx.x & 31;
    unsigned int gwarp = blockIdx.x * (PT_BLOCK / 32) + (threadIdx.x >> 5);
    unsigned int nwarps = gridDim.x * (PT_BLOCK / 32);

    for (unsigned int p = gwarp; p < n; p += nwarps) {
        int b, h, w; decode_pt(g_pts[p], b, h, w);
        #pragma unroll
        for (int it = 0; it < NITER; it++) {
            int k = it * 32 + lane;
            if (k < WINSQ) {
                int dy = k / WIN - R;
                int dx = k - (k / WIN) * WIN - R;
                int y = h + dy, xx = w + dx;
                if ((unsigned)y < HH && (unsigned)xx < WW)
                    g_scratch[b * PLANE + y * WW + xx] = 0.f;
            }
        }
    }
}

// ---------------------------------------------------------------------------
extern "C" void kernel_launch(void* const* d_in, const int* in_sizes, int n_in,
                              void* d_out, int out_size) {
    const float* x = (const float*)d_in[0];
    float* out = (float*)d_out;

    int n_f4 = (BB * CC * PLANE) / 4;          // 8,388,608
    k_copy_collect<<<n_f4 / 256, 256>>>(x, out);

    k_splat_max<<<PT_GRID, PT_BLOCK>>>();
    k_write<<<PT_GRID, PT_BLOCK>>>(out);
    k_zero_reset<<<PT_GRID, PT_BLOCK>>>();
}

// round 6
// speedup vs baseline: 1.6078x; 1.5075x over previous
#include <cuda_runtime.h>

// Problem constants (fixed shapes from reference setup_inputs)
#define BB 32
#define CC 4
#define HH 512
#define WW 512
#define PLANE (HH * WW)            // 262144
#define R 6                        // truncation radius: exp(-0.5*7^2)=2.3e-11, negligible
#define WIN (2 * R + 1)            // 13
#define WINSQ (WIN * WIN)          // 169
#define MAXPTS 65536
#define PT_BLOCK 256               // 8 warps/block, warp-per-point
#define PT_GRID 1100               // 8800 warps >= expected ~8400 points (one wave)
#define NITER 6                    // ceil(169/32)

// Gaussian LUT: exp(-0.5*k^2), k = 0..6 (sigma = 1)
__device__ const float d_g[R + 1] = {
    1.0f,
    6.0653065971e-01f,
    1.3533528324e-01f,
    1.1108996538e-02f,
    3.3546262790e-04f,
    3.7266531720e-06f,
    1.5229979745e-08f
};

// Persistent state (BSS zero-init at module load).
// Cross-replay invariants:
//   g_cnt == 0 at entry   (reset by k_normalize of the previous call)
//   g_mbits == 0 by the time k_splat_max runs (reset inside k_copy_collect)
__device__ unsigned int g_pts[MAXPTS];           // packed: (b<<18) | (h*512+w)
__device__ unsigned int g_cnt;
__device__ unsigned int g_mbits[BB];             // per-batch max (uint bits, vals >= 0)

// ---------------------------------------------------------------------------
// Vectorized copy; channel 2 written as zeros, positives pushed to point list.
// Also resets g_mbits (this kernel never reads it; consumer is the next kernel).
__global__ void k_copy_collect(const float* __restrict__ x, float* __restrict__ out) {
    if (blockIdx.x == 0 && threadIdx.x < BB) g_mbits[threadIdx.x] = 0u;

    int idx = blockIdx.x * blockDim.x + threadIdx.x;      // float4 index
    int f = idx << 2;
    int plane = f >> 18;                                  // PLANE = 2^18
    int c = plane & 3;

    float4 v = reinterpret_cast<const float4*>(x)[idx];

    if (c == 2) {
        int b = plane >> 2;
        int off = f & (PLANE - 1);
        reinterpret_cast<float4*>(out)[idx] = make_float4(0.f, 0.f, 0.f, 0.f);
        float vals[4] = {v.x, v.y, v.z, v.w};
        #pragma unroll
        for (int k = 0; k < 4; k++) {
            if (vals[k] > 0.f) {
                unsigned int p = ((unsigned)b << 18) | (unsigned)(off + k);
                unsigned int i = atomicAdd(&g_cnt, 1u);
                if (i < MAXPTS) g_pts[i] = p;
            }
        }
    } else {
        reinterpret_cast<float4*>(out)[idx] = v;
    }
}

// ---------------------------------------------------------------------------
// Splat truncated Gaussians straight into out channel 2 (zeroed by the copy
// kernel) and compute the per-batch max in the same pass. Warp-per-point.
//
// Max trick: atomicAdd returns the pre-add value; weights are positive, so a
// pixel's running value is monotone increasing and the chronologically last
// adder observes (old + wgt) == the pixel's final value. Every candidate is
// <= its pixel's final value and each final value IS some candidate, so
// max(candidates) == max(final G). One atomicMax per point.
__global__ void k_splat_max(float* __restrict__ out) {
    __shared__ float wtab[WINSQ];
    for (int k = threadIdx.x; k < WINSQ; k += PT_BLOCK) {
        int dy = k / WIN - R;
        int dx = k - (k / WIN) * WIN - R;
        wtab[k] = d_g[dy < 0 ? -dy : dy] * d_g[dx < 0 ? -dx : dx];
    }
    __syncthreads();

    unsigned int n = min(g_cnt, (unsigned int)MAXPTS);
    int lane = threadIdx.x & 31;
    unsigned int gwarp = blockIdx.x * (PT_BLOCK / 32) + (threadIdx.x >> 5);
    unsigned int nwarps = gridDim.x * (PT_BLOCK / 32);

    for (unsigned int p = gwarp; p < n; p += nwarps) {
        unsigned int pt = g_pts[p];
        int b = (int)(pt >> 18);
        int o = (int)(pt & 0x3FFFFu);
        int h = o >> 9, w = o & 511;
        float* plane2 = out + ((size_t)(b * CC + 2)) * PLANE;

        float cand = 0.f;
        #pragma unroll
        for (int it = 0; it < NITER; it++) {
            int k = it * 32 + lane;
            if (k < WINSQ) {
                int dy = k / WIN - R;
                int dx = k - (k / WIN) * WIN - R;
                int y = h + dy, xx = w + dx;
                if ((unsigned)y < HH && (unsigned)xx < WW) {
                    float wgt = wtab[k];
                    float old = atomicAdd(&plane2[y * WW + xx], wgt);
                    cand = fmaxf(cand, old + wgt);
                }
            }
        }
        #pragma unroll
        for (int s = 16; s; s >>= 1)
            cand = fmaxf(cand, __shfl_xor_sync(0xFFFFFFFFu, cand, s));
        if (lane == 0) atomicMax(&g_mbits[b], __float_as_uint(cand));
    }
}

// ---------------------------------------------------------------------------
// Dense normalize of channel 2: out *= 1/m[b]. Pixels never splatted are 0 and
// stay 0. Also resets g_cnt for the next replay (this kernel never reads it).
__global__ void k_normalize(float* __restrict__ out) {
    if (blockIdx.x == 0 && threadIdx.x == 0) g_cnt = 0u;

    __shared__ float s_inv;
    // Each block covers 256 consecutive float4 within a single batch's plane
    // (PLANE/4 = 65536 float4 per batch; 256 blocks per batch, aligned).
    int b = blockIdx.x >> 8;                       // 256 blocks per batch
    if (threadIdx.x == 0) {
        float m = __uint_as_float(g_mbits[b]);
        s_inv = (m > 0.f) ? (1.0f / m) : 1.0f;
    }
    __syncthreads();
    float inv = s_inv;

    int local = (blockIdx.x & 255) * 256 + threadIdx.x;   // float4 index in plane
    float4* p = reinterpret_cast<float4*>(out + ((size_t)(b * CC + 2)) * PLANE) + local;
    float4 v = *p;
    v.x *= inv; v.y *= inv; v.z *= inv; v.w *= inv;
    *p = v;
}

// ---------------------------------------------------------------------------
extern "C" void kernel_launch(void* const* d_in, const int* in_sizes, int n_in,
                              void* d_out, int out_size) {
    const float* x = (const float*)d_in[0];
    float* out = (float*)d_out;

    int n_f4 = (BB * CC * PLANE) / 4;          // 8,388,608
    k_copy_collect<<<n_f4 / 256, 256>>>(x, out);

    k_splat_max<<<PT_GRID, PT_BLOCK>>>(out);

    k_normalize<<<BB * 256, 256>>>(out);       // 8192 blocks, 1 batch per 256 blocks
}

// round 7
// speedup vs baseline: 1.7567x; 1.0926x over previous
#include <cuda_runtime.h>

// Problem constants (fixed shapes from reference setup_inputs)
#define BB 32
#define CC 4
#define HH 512
#define WW 512
#define PLANE (HH * WW)            // 262144
#define F4_PER_PLANE (PLANE / 4)   // 65536
#define R 6                        // truncation: exp(-0.5*7^2)=2.3e-11, below rel-err scale
#define WIN (2 * R + 1)            // 13
#define WINSQ (WIN * WIN)          // 169
#define MAXPTS 65536
#define PT_BLOCK 256               // 8 warps/block, warp-per-point
#define PT_GRID 1100               // 8800 warps >= expected ~8400 points (one wave)
#define NITER 6                    // ceil(169/32)

// Copy kernel geometry: 256 threads x 2 float4 each = 512 f4 per block
// => 128 blocks per plane, 128 planes total => 16384 blocks.
#define CP_BLOCK 256
#define BLK_PER_PLANE 128
#define NONCH2_BLOCKS (96 * BLK_PER_PLANE)   // 12288: 96 non-ch2 planes first
#define CP_GRID (128 * BLK_PER_PLANE)        // 16384: ch2 planes last (L2-resident after)

// Gaussian LUT: exp(-0.5*k^2), k = 0..6 (sigma = 1)
__device__ const float d_g[R + 1] = {
    1.0f,
    6.0653065971e-01f,
    1.3533528324e-01f,
    1.1108996538e-02f,
    3.3546262790e-04f,
    3.7266531720e-06f,
    1.5229979745e-08f
};

// Persistent state (BSS zero-init at module load).
// Cross-replay invariants:
//   g_cnt == 0 at entry            (reset by k_normalize of the previous call)
//   g_mbits == 0 before k_splat_max (reset inside k_copy_collect)
__device__ unsigned int g_pts[MAXPTS];           // packed: (b<<18) | (h*512+w)
__device__ unsigned int g_cnt;
__device__ unsigned int g_n;                     // snapshot, set by k_splat_max
__device__ unsigned int g_mbits[BB];             // per-batch max (uint bits, vals >= 0)

// ---------------------------------------------------------------------------
// Plane-remapped, ILP-2 copy. Blocks [0, NONCH2_BLOCKS) stream-copy the 96
// non-ch2 planes (uniform, branch-free, L2-bypass hints). Blocks
// [NONCH2_BLOCKS, CP_GRID) handle the 32 ch2 planes LAST: they write zeros
// with default caching so ch2 stays L2-resident for splat + normalize, and
// collect positive mask entries into the point list.
__global__ void k_copy_collect(const float* __restrict__ x, float* __restrict__ out) {
    if (blockIdx.x == 0 && threadIdx.x < BB) g_mbits[threadIdx.x] = 0u;

    const float4* __restrict__ xi = reinterpret_cast<const float4*>(x);
    float4* __restrict__ oo = reinterpret_cast<float4*>(out);

    unsigned int g = blockIdx.x;
    int tid = threadIdx.x;

    if (g < NONCH2_BLOCKS) {
        // plane index among {c=0,1,3} x 32 batches
        int pi = g >> 7;                 // 0..95
        int blk = g & (BLK_PER_PLANE - 1);
        int b = pi / 3;
        int c3 = pi - b * 3;
        int c = (c3 == 2) ? 3 : c3;      // {0,1,3}
        size_t pb = (size_t)(b * CC + c) * F4_PER_PLANE;
        size_t f4a = pb + blk * 512 + tid;
        float4 va = __ldcs(xi + f4a);
        float4 vb = __ldcs(xi + f4a + 256);
        __stcs(oo + f4a, va);
        __stcs(oo + f4a + 256, vb);
    } else {
        unsigned int g2 = g - NONCH2_BLOCKS;
        int b = g2 >> 7;                 // 0..31
        int blk = g2 & (BLK_PER_PLANE - 1);
        size_t pb = (size_t)(b * CC + 2) * F4_PER_PLANE;
        int eoff = (blk * 512 + tid) * 4;          // element offset within plane
        size_t f4a = pb + blk * 512 + tid;
        float4 va = __ldcs(xi + f4a);
        float4 vb = __ldcs(xi + f4a + 256);
        float4 z = make_float4(0.f, 0.f, 0.f, 0.f);
        oo[f4a] = z;                                  // default caching: keep in L2
        oo[f4a + 256] = z;
        float vals[8] = {va.x, va.y, va.z, va.w, vb.x, vb.y, vb.z, vb.w};
        #pragma unroll
        for (int k = 0; k < 8; k++) {
            if (vals[k] > 0.f) {
                int off = eoff + (k < 4 ? k : 1024 + (k - 4));
                unsigned int p = ((unsigned)b << 18) | (unsigned)off;
                unsigned int i = atomicAdd(&g_cnt, 1u);
                if (i < MAXPTS) g_pts[i] = p;
            }
        }
    }
}

// ---------------------------------------------------------------------------
// Splat truncated Gaussians straight into out channel 2 (zeroed, L2-resident)
// and compute the per-batch max in the same pass. Warp-per-point.
//
// Max trick: atomicAdd returns the pre-add value; weights are positive, so a
// pixel's running value is monotone increasing and the chronologically last
// adder observes (old + wgt) == the pixel's final value. Every candidate is
// <= its pixel's final value and each final value IS some candidate, so
// max(candidates) == max(final G). One atomicMax per point.
__global__ void k_splat_max(float* __restrict__ out) {
    __shared__ float wtab[WINSQ];
    for (int k = threadIdx.x; k < WINSQ; k += PT_BLOCK) {
        int dy = k / WIN - R;
        int dx = k - (k / WIN) * WIN - R;
        wtab[k] = d_g[dy < 0 ? -dy : dy] * d_g[dx < 0 ? -dx : dx];
    }
    __syncthreads();

    unsigned int n = min(g_cnt, (unsigned int)MAXPTS);
    if (blockIdx.x == 0 && threadIdx.x == 0) g_n = n;   // snapshot for k_normalize

    int lane = threadIdx.x & 31;
    unsigned int gwarp = blockIdx.x * (PT_BLOCK / 32) + (threadIdx.x >> 5);
    unsigned int nwarps = gridDim.x * (PT_BLOCK / 32);

    for (unsigned int p = gwarp; p < n; p += nwarps) {
        unsigned int pt = g_pts[p];
        int b = (int)(pt >> 18);
        int o = (int)(pt & 0x3FFFFu);
        int h = o >> 9, w = o & 511;
        float* plane2 = out + ((size_t)(b * CC + 2)) * PLANE;

        float cand = 0.f;
        #pragma unroll
        for (int it = 0; it < NITER; it++) {
            int k = it * 32 + lane;
            if (k < WINSQ) {
                int dy = k / WIN - R;
                int dx = k - (k / WIN) * WIN - R;
                int y = h + dy, xx = w + dx;
                if ((unsigned)y < HH && (unsigned)xx < WW) {
                    float wgt = wtab[k];
                    float old = atomicAdd(&plane2[y * WW + xx], wgt);
                    cand = fmaxf(cand, old + wgt);
                }
            }
        }
        #pragma unroll
        for (int s = 16; s; s >>= 1)
            cand = fmaxf(cand, __shfl_xor_sync(0xFFFFFFFFu, cand, s));
        if (lane == 0) atomicMax(&g_mbits[b], __float_as_uint(cand));
    }
}

// ---------------------------------------------------------------------------
// Dense normalize of channel 2 (mostly L2-resident): out *= 1/m[b]. Pixels
// never splatted are 0 and stay 0. Resets g_cnt for the next replay (this
// kernel reads only the g_n snapshot-independent g_mbits, never g_cnt).
__global__ void k_normalize(float* __restrict__ out) {
    if (blockIdx.x == 0 && threadIdx.x == 0) g_cnt = 0u;

    __shared__ float s_inv;
    int b = blockIdx.x >> 8;                       // 256 blocks per batch
    if (threadIdx.x == 0) {
        float m = __uint_as_float(g_mbits[b]);
        s_inv = (m > 0.f) ? (1.0f / m) : 1.0f;
    }
    __syncthreads();
    float inv = s_inv;

    int local = (blockIdx.x & 255) * 256 + threadIdx.x;   // float4 index in plane
    float4* p = reinterpret_cast<float4*>(out + ((size_t)(b * CC + 2)) * PLANE) + local;
    float4 v = *p;
    v.x *= inv; v.y *= inv; v.z *= inv; v.w *= inv;
    *p = v;
}

// ---------------------------------------------------------------------------
extern "C" void kernel_launch(void* const* d_in, const int* in_sizes, int n_in,
                              void* d_out, int out_size) {
    const float* x = (const float*)d_in[0];
    float* out = (float*)d_out;

    k_copy_collect<<<CP_GRID, CP_BLOCK>>>(x, out);
    k_splat_max<<<PT_GRID, PT_BLOCK>>>(out);
    k_normalize<<<BB * 256, 256>>>(out);       // 8192 blocks, 256 per batch
}